// round 14
// baseline (speedup 1.0000x reference)
#include <cuda_runtime.h>
#include <cuda_bf16.h>
#include <cstdint>

// ---------------- problem constants ----------------
#define NN    1024
#define DD    384
#define KK    64
#define POSW  15
#define NBINS 64
#define NDEPTH 4
#define BSZ   256
#define NCBX  12           // column blocks (384/32)
#define NPART (NCBX * 2)   // pos-partial slots: col-block x warp N-half
#define DDP   (DD / 2)     // packed k-pairs per row

// ---------------- persistent device scratch ----------------
__device__ float    g_based[NN * BSZ];
__device__ float    g_local[NN * DD];           // fp32 master (only copy)
__device__ uint32_t g_msgHP[NN * DDP];          // bf16x2 hi of msg (k-pairs)
__device__ uint32_t g_msgLP[NN * DDP];          // bf16x2 lo of msg
__device__ uint32_t g_WnHP[DDP * DD];           // bf16x2 hi of Wn, [kp][n]
__device__ uint32_t g_WnLP[DDP * DD];           // bf16x2 lo of Wn
__device__ float    g_pos[NN * POSW];
__device__ float    g_pospart[NPART * NN * POSW];

// ---------------- threefry2x32 (bit-exact JAX) ----------------
__host__ __device__ __forceinline__ uint32_t rotl32(uint32_t x, int r) {
    return (x << r) | (x >> (32 - r));
}

__host__ __device__ __forceinline__ void tf2x32(uint32_t k0, uint32_t k1,
                                                uint32_t x0, uint32_t x1,
                                                uint32_t& o0, uint32_t& o1) {
    uint32_t ks2 = k0 ^ k1 ^ 0x1BD11BDAu;
#define TFR(r) { x0 += x1; x1 = rotl32(x1, r); x1 ^= x0; }
    x0 += k0;  x1 += k1;
    TFR(13) TFR(15) TFR(26) TFR(6)
    x0 += k1;  x1 += ks2 + 1u;
    TFR(17) TFR(29) TFR(16) TFR(24)
    x0 += ks2; x1 += k0 + 2u;
    TFR(13) TFR(15) TFR(26) TFR(6)
    x0 += k0;  x1 += k1 + 3u;
    TFR(17) TFR(29) TFR(16) TFR(24)
    x0 += k1;  x1 += ks2 + 4u;
    TFR(13) TFR(15) TFR(26) TFR(6)
    x0 += ks2; x1 += k0 + 5u;
#undef TFR
    o0 = x0; o1 = x1;
}

__device__ __forceinline__ float gumbel_from_bits(uint32_t b) {
    float u = __uint_as_float(0x3F800000u | (b >> 9)) - 1.0f;
    return -logf(-logf(u + 1e-6f) + 1e-6f);
}

// bf16 hi/lo split helpers
__device__ __forceinline__ void bf16_split(float v, uint16_t& h, uint16_t& l) {
    __nv_bfloat16 hb = __float2bfloat16(v);
    float lr = v - __bfloat162float(hb);
    __nv_bfloat16 lb = __float2bfloat16(lr);
    h = *reinterpret_cast<uint16_t*>(&hb);
    l = *reinterpret_cast<uint16_t*>(&lb);
}

__device__ __forceinline__ void mma_bf16(float* c, const uint32_t* a, const uint32_t* b) {
    asm volatile(
        "mma.sync.aligned.m16n8k16.row.col.f32.bf16.bf16.f32 "
        "{%0,%1,%2,%3},{%4,%5,%6,%7},{%8,%9},{%0,%1,%2,%3};"
        : "+f"(c[0]), "+f"(c[1]), "+f"(c[2]), "+f"(c[3])
        : "r"(a[0]), "r"(a[1]), "r"(a[2]), "r"(a[3]), "r"(b[0]), "r"(b[1]));
}

// ---------------- prep: Wn -> packed bf16x2 hi/lo [kp][n] --------------
__global__ void prep_kernel(const float* __restrict__ Wn) {
    int idx = blockIdx.x * 256 + threadIdx.x;
    if (idx >= DDP * DD) return;
    int kp = idx / DD;
    int n  = idx % DD;
    float v0 = Wn[(size_t)(2 * kp) * DD + n];
    float v1 = Wn[(size_t)(2 * kp + 1) * DD + n];
    uint16_t h0, l0, h1, l1;
    bf16_split(v0, h0, l0);
    bf16_split(v1, h1, l1);
    g_WnHP[idx] = (uint32_t)h0 | ((uint32_t)h1 << 16);
    g_WnLP[idx] = (uint32_t)l0 | ((uint32_t)l1 << 16);
}

// ---------------- kernel: step-invariant base distance ----------------
__global__ void based_kernel(const float* __restrict__ prev_pos,
                             const float* __restrict__ disto,
                             const int* __restrict__ resi,
                             const int* __restrict__ chain,
                             const int* __restrict__ batch) {
    int gid = blockIdx.x * blockDim.x + threadIdx.x;
    if (gid >= NN * BSZ) return;
    int i  = gid >> 8;
    int jj = gid & 255;
    int b  = batch[i];
    int j  = b * BSZ + jj;

    const float4* dp = (const float4*)(disto + ((size_t)i * NN + j) * NBINS);
    float4 v[16];
    float mx = -1e30f;
#pragma unroll
    for (int q = 0; q < 16; q++) {
        v[q] = dp[q];
        mx = fmaxf(mx, fmaxf(fmaxf(v[q].x, v[q].y), fmaxf(v[q].z, v[q].w)));
    }
    const float step = 22.0f / 64.0f;
    float se = 0.0f, swc = 0.0f;
#pragma unroll
    for (int q = 0; q < 16; q++) {
        float e0 = expf(v[q].x - mx), e1 = expf(v[q].y - mx);
        float e2 = expf(v[q].z - mx), e3 = expf(v[q].w - mx);
        se  += e0 + e1 + e2 + e3;
        swc += e0 * (step * (4*q + 0) + 0.5f*step)
             + e1 * (step * (4*q + 1) + 0.5f*step)
             + e2 * (step * (4*q + 2) + 0.5f*step)
             + e3 * (step * (4*q + 3) + 0.5f*step);
    }
    float md = swc / se;

    float d = __int_as_float(0x7f800000);
    if (chain[i] == chain[j]) {
        d = fabsf((float)(resi[i] - resi[j])) * 3.81f;
    }
    if (md < 8.0f) d = fminf(d, md);

    float dx = prev_pos[i * POSW + 3] - prev_pos[j * POSW + 3];
    float dy = prev_pos[i * POSW + 4] - prev_pos[j * POSW + 4];
    float dz = prev_pos[i * POSW + 5] - prev_pos[j * POSW + 5];
    d = fminf(d, sqrtf(dx * dx + dy * dy + dz * dz));

    g_based[gid] = d;
}

// -------- fused top-K (hybrid shfl bitonic) + gather -> packed msg -----
__global__ void __launch_bounds__(384) topk_msg_kernel(uint32_t k0, uint32_t k1,
                                                       const int* __restrict__ batch) {
    int i   = blockIdx.x;
    int tid = threadIdx.x;                                 // 384 threads
    int b   = batch[i];
    bool act = tid < BSZ;

    __shared__ unsigned long long s[BSZ];
    __shared__ int sidx[KK];

    unsigned long long K = ~0ull;
    if (act) {
        int jj = tid;
        int j  = b * BSZ + jj;
        float cx = g_pos[i * POSW + 3], cy = g_pos[i * POSW + 4], cz = g_pos[i * POSW + 5];
        float dx = cx - g_pos[j * POSW + 3];
        float dy = cy - g_pos[j * POSW + 4];
        float dz = cz - g_pos[j * POSW + 5];
        float d  = fminf(g_based[i * BSZ + jj], sqrtf(dx * dx + dy * dy + dz * dz));

        uint32_t o0, o1;
        tf2x32(k0, k1, 0u, (uint32_t)(i * NN + j), o0, o1);
        float g = gumbel_from_bits(o0 ^ o1);
        float rd = 3.0f * d - g;

        uint32_t ub = __float_as_uint(rd);
        ub = (ub & 0x80000000u) ? ~ub : (ub | 0x80000000u);
        K = ((unsigned long long)ub << 32) | (unsigned)tid;
    }

    for (unsigned k = 2; k <= BSZ; k <<= 1) {
        bool up = ((tid & k) == 0);
        for (unsigned st = k >> 1; st > 0; st >>= 1) {
            if (st >= 32) {
                if (act) s[tid] = K;
                __syncthreads();
                unsigned long long other = act ? s[tid ^ st] : 0ull;
                __syncthreads();
                if (act) {
                    bool lower = ((tid & st) == 0);
                    bool keepmin = (up == lower);
                    K = keepmin ? (K < other ? K : other) : (K > other ? K : other);
                }
            } else if (act) {
                unsigned long long other = __shfl_xor_sync(0xFFFFFFFFu, K, st);
                bool lower = ((tid & st) == 0);
                bool keepmin = (up == lower);
                K = keepmin ? (K < other ? K : other) : (K > other ? K : other);
            }
        }
    }

    if (tid < KK)
        sidx[tid] = b * BSZ + (int)(K & 0xffffffffu);
    __syncthreads();

    float acc = 0.0f;
#pragma unroll 8
    for (int k = 0; k < KK; k++)
        acc += g_local[sidx[k] * DD + tid];
    float m = acc * (1.0f / 64.0f);

    uint16_t h, l;
    bf16_split(m, h, l);
    uint32_t ho = __shfl_xor_sync(0xFFFFFFFFu, (uint32_t)h, 1);
    uint32_t lo = __shfl_xor_sync(0xFFFFFFFFu, (uint32_t)l, 1);
    if ((tid & 1) == 0) {
        g_msgHP[i * DDP + (tid >> 1)] = (uint32_t)h | (ho << 16);
        g_msgLP[i * DDP + (tid >> 1)] = (uint32_t)l | (lo << 16);
    }
}

// -------- main GEMM: local += gelu(msg @ Wn), bf16x3, 64x32 tiles ------
__device__ __forceinline__ float gelu_tanh(float x) {
    float x3 = x * x * x;
    float t = tanhf(0.7978845608028654f * (x + 0.044715f * x3));
    return 0.5f * x * (1.0f + t);
}

#define KPB   16   // packed k-pairs per k-block (= 32 floats)
#define AST   20   // A[m][kp] stride: 20 ≡ 4 mod 32 -> conflict-free
#define BST   40   // B[kp][n] stride: 40 ≡ 8 mod 32 -> conflict-free
#define NKIT  (DDP / KPB)   // 12

__global__ void __launch_bounds__(256) gemm_gelu_tc(const float* __restrict__ Wp) {
    __shared__ uint32_t AsH[2][64 * AST];    // 10.24 KB
    __shared__ uint32_t AsL[2][64 * AST];    // 10.24 KB
    __shared__ uint32_t BsH[2][KPB * BST];   //  5.12 KB
    __shared__ uint32_t BsL[2][KPB * BST];   //  5.12 KB
    __shared__ float    WpS[32 * POSW];      //  1.92 KB  (~32.6 KB total)

    int tid  = threadIdx.x;
    int warp = tid >> 5, lane = tid & 31;
    int wm = (warp & 3) * 16;            // 8 warps: 4 M x 2 N of 16x16 tiles
    int wn = (warp >> 2) * 16;
    int row0 = blockIdx.y * 64;
    int col0 = blockIdx.x * 32;
    int g  = lane >> 2;
    int tg = lane & 3;

    float accA[2][4] = {};               // kp block 0..7
    float accB[2][4] = {};               // kp block 8..15

    // staging (256 threads)
    int am  = tid >> 2;            // 0..63
    int akp = (tid & 3) * 4;       // 0,4,8,12 (16B per A array)
    int bkp = tid >> 4;            // 0..15
    int bn  = (tid & 15) * 2;      // 0..30 (8B per B array)

    uint32_t sah[2], sal[2], sbh[2], sbl[2];
#pragma unroll
    for (int u = 0; u < 2; u++) {
        sah[u] = (uint32_t)__cvta_generic_to_shared(&AsH[u][am * AST + akp]);
        sal[u] = (uint32_t)__cvta_generic_to_shared(&AsL[u][am * AST + akp]);
        sbh[u] = (uint32_t)__cvta_generic_to_shared(&BsH[u][bkp * BST + bn]);
        sbl[u] = (uint32_t)__cvta_generic_to_shared(&BsL[u][bkp * BST + bn]);
    }

#define GSTAGE(it, buf)                                                          \
    {                                                                            \
        int k0p = (it) * KPB;                                                    \
        const uint32_t* pah = &g_msgHP[(row0 + am) * DDP + k0p + akp];           \
        asm volatile("cp.async.ca.shared.global [%0],[%1],16;" :: "r"(sah[buf]), "l"(pah)); \
        const uint32_t* pal = &g_msgLP[(row0 + am) * DDP + k0p + akp];           \
        asm volatile("cp.async.ca.shared.global [%0],[%1],16;" :: "r"(sal[buf]), "l"(pal)); \
        const uint32_t* pbh = &g_WnHP[(size_t)(k0p + bkp) * DD + col0 + bn];     \
        asm volatile("cp.async.ca.shared.global [%0],[%1],8;" :: "r"(sbh[buf]), "l"(pbh)); \
        const uint32_t* pbl = &g_WnLP[(size_t)(k0p + bkp) * DD + col0 + bn];     \
        asm volatile("cp.async.ca.shared.global [%0],[%1],8;" :: "r"(sbl[buf]), "l"(pbl)); \
        asm volatile("cp.async.commit_group;");                                  \
    }

    GSTAGE(0, 0)

    for (int idx = tid; idx < 32 * POSW; idx += 256)
        WpS[idx] = Wp[col0 * POSW + idx];

    for (int it = 0; it < NKIT; ++it) {
        int cur = it & 1;
        if (it + 1 < NKIT) {
            GSTAGE(it + 1, !cur)
            asm volatile("cp.async.wait_group 1;");
        } else {
            asm volatile("cp.async.wait_group 0;");
        }
        __syncthreads();

        const uint32_t* AH = AsH[cur];
        const uint32_t* AL = AsL[cur];
        const uint32_t* BH = BsH[cur];
        const uint32_t* BL = BsL[cur];
#pragma unroll
        for (int ksp = 0; ksp < KPB; ksp += 8) {       // kp octets (k16 per MMA)
            float (*acc)[4] = (ksp == 0) ? accA : accB;
            uint32_t ah[4] = {
                AH[(wm + g) * AST + ksp + tg],
                AH[(wm + g + 8) * AST + ksp + tg],
                AH[(wm + g) * AST + ksp + tg + 4],
                AH[(wm + g + 8) * AST + ksp + tg + 4] };
            uint32_t al[4] = {
                AL[(wm + g) * AST + ksp + tg],
                AL[(wm + g + 8) * AST + ksp + tg],
                AL[(wm + g) * AST + ksp + tg + 4],
                AL[(wm + g + 8) * AST + ksp + tg + 4] };
#pragma unroll
            for (int nj = 0; nj < 2; nj++) {
                int cc = wn + nj * 8 + g;
                uint32_t bh[2] = { BH[(ksp + tg) * BST + cc],
                                   BH[(ksp + tg + 4) * BST + cc] };
                uint32_t bl[2] = { BL[(ksp + tg) * BST + cc],
                                   BL[(ksp + tg + 4) * BST + cc] };
                mma_bf16(acc[nj], al, bh);
                mma_bf16(acc[nj], ah, bl);
                mma_bf16(acc[nj], ah, bh);
            }
        }
        __syncthreads();
    }

    // merge split accumulators
#pragma unroll
    for (int nj = 0; nj < 2; nj++)
#pragma unroll
        for (int q = 0; q < 4; q++)
            accA[nj][q] += accB[nj][q];

    // epilogue: local += gelu(acc); pos partials
    int r = row0 + wm + g;
    float pp0[POSW], pp1[POSW];
#pragma unroll
    for (int o = 0; o < POSW; o++) { pp0[o] = 0.0f; pp1[o] = 0.0f; }

#pragma unroll
    for (int nj = 0; nj < 2; nj++) {
        int cl = wn + nj * 8 + 2 * tg;
        int c  = col0 + cl;
        float v00 = g_local[r * DD + c]           + gelu_tanh(accA[nj][0]);
        float v01 = g_local[r * DD + c + 1]       + gelu_tanh(accA[nj][1]);
        float v10 = g_local[(r + 8) * DD + c]     + gelu_tanh(accA[nj][2]);
        float v11 = g_local[(r + 8) * DD + c + 1] + gelu_tanh(accA[nj][3]);
        g_local[r * DD + c]           = v00;
        g_local[r * DD + c + 1]       = v01;
        g_local[(r + 8) * DD + c]     = v10;
        g_local[(r + 8) * DD + c + 1] = v11;
#pragma unroll
        for (int o = 0; o < POSW; o++) {
            float w0 = WpS[cl * POSW + o];
            float w1 = WpS[(cl + 1) * POSW + o];
            pp0[o] += v00 * w0 + v01 * w1;
            pp1[o] += v10 * w0 + v11 * w1;
        }
    }

#pragma unroll
    for (int dlt = 1; dlt <= 2; dlt <<= 1)
#pragma unroll
        for (int o = 0; o < POSW; o++) {
            pp0[o] += __shfl_xor_sync(0xFFFFFFFFu, pp0[o], dlt);
            pp1[o] += __shfl_xor_sync(0xFFFFFFFFu, pp1[o], dlt);
        }

    if (tg == 0) {
        int slot = blockIdx.x * 2 + (wn >> 4);   // col-block x N-half
        float* pb = &g_pospart[(size_t)slot * (NN * POSW)];
#pragma unroll
        for (int o = 0; o < POSW; o++) {
            pb[r * POSW + o]       = pp0[o];
            pb[(r + 8) * POSW + o] = pp1[o];
        }
    }
}

// ---------------- kernel: finalize pos + trajectory write --------------
__global__ void __launch_bounds__(256) finalize_pos(float* __restrict__ traj_out) {
    int gidx = blockIdx.x * 256 + threadIdx.x;             // 60 x 256 = 15360
    float acc = 0.0f;
#pragma unroll
    for (int cb = 0; cb < NPART; cb++)
        acc += g_pospart[(size_t)cb * (NN * POSW) + gidx];
    float p = g_pos[gidx] + 0.1f * acc;
    g_pos[gidx] = p;
    traj_out[gidx] = p;
}

// ---------------- launch ----------------
extern "C" void kernel_launch(void* const* d_in, const int* in_sizes, int n_in,
                              void* d_out, int out_size) {
    const float* local    = (const float*)d_in[0];
    const float* pos      = (const float*)d_in[1];
    const float* prev_pos = (const float*)d_in[2];
    const float* disto    = (const float*)d_in[3];
    const float* Wn       = (const float*)d_in[4];
    const float* Wp       = (const float*)d_in[5];
    const int*   resi     = (const int*)d_in[6];
    const int*   chain    = (const int*)d_in[7];
    const int*   batch    = (const int*)d_in[8];
    float* out = (float*)d_out;

    cudaMemcpyToSymbolAsync(g_local, local, (size_t)NN * DD * sizeof(float), 0,
                            cudaMemcpyDeviceToDevice, 0);
    cudaMemcpyToSymbolAsync(g_pos, pos, (size_t)NN * POSW * sizeof(float), 0,
                            cudaMemcpyDeviceToDevice, 0);

    prep_kernel<<<(DDP * DD + 255) / 256, 256>>>(Wn);
    based_kernel<<<NN * BSZ / 256, 256>>>(prev_pos, disto, resi, chain, batch);

    uint32_t fk0[NDEPTH], fk1[NDEPTH];
    for (int t = 0; t < NDEPTH; t++)
        tf2x32(0u, 42u, 0u, (uint32_t)t, fk0[t], fk1[t]);

    float* traj_base = out + (size_t)NN * DD + (size_t)NN * POSW;
    dim3 ggrid(DD / 32, NN / 64);   // (12, 16) = 192 CTAs

    for (int t = 0; t < NDEPTH; t++) {
        topk_msg_kernel<<<NN, 384>>>(fk0[t], fk1[t], batch);
        gemm_gelu_tc<<<ggrid, 256>>>(Wp);
        finalize_pos<<<NN * POSW / 256, 256>>>(traj_base + (size_t)t * NN * POSW);
    }

    cudaMemcpyFromSymbolAsync(out, g_local, (size_t)NN * DD * sizeof(float), 0,
                              cudaMemcpyDeviceToDevice, 0);
    cudaMemcpyFromSymbolAsync(out + (size_t)NN * DD, g_pos,
                              (size_t)NN * POSW * sizeof(float), 0,
                              cudaMemcpyDeviceToDevice, 0);
}

// round 15
// speedup vs baseline: 1.0595x; 1.0595x over previous
#include <cuda_runtime.h>
#include <cuda_bf16.h>
#include <cstdint>

// ---------------- problem constants ----------------
#define NN    1024
#define DD    384
#define KK    64
#define POSW  15
#define NBINS 64
#define NDEPTH 4
#define BSZ   256
#define NCB   6            // column blocks (384/64)
#define NPART NCB          // pos-partial slots: one per col-block (reduced in-kernel)
#define DDP   (DD / 2)     // packed k-pairs per row

// ---------------- persistent device scratch ----------------
__device__ float    g_based[NN * BSZ];
__device__ float    g_local[NN * DD];           // fp32 master (only copy)
__device__ uint32_t g_msgHP[NN * DDP];          // bf16x2 hi of msg (k-pairs)
__device__ uint32_t g_msgLP[NN * DDP];          // bf16x2 lo of msg
__device__ uint32_t g_WnHP[DDP * DD];           // bf16x2 hi of Wn, [kp][n]
__device__ uint32_t g_WnLP[DDP * DD];           // bf16x2 lo of Wn
__device__ float    g_pos[NN * POSW];
__device__ float    g_pospart[NPART * NN * POSW];

// ---------------- threefry2x32 (bit-exact JAX) ----------------
__host__ __device__ __forceinline__ uint32_t rotl32(uint32_t x, int r) {
    return (x << r) | (x >> (32 - r));
}

__host__ __device__ __forceinline__ void tf2x32(uint32_t k0, uint32_t k1,
                                                uint32_t x0, uint32_t x1,
                                                uint32_t& o0, uint32_t& o1) {
    uint32_t ks2 = k0 ^ k1 ^ 0x1BD11BDAu;
#define TFR(r) { x0 += x1; x1 = rotl32(x1, r); x1 ^= x0; }
    x0 += k0;  x1 += k1;
    TFR(13) TFR(15) TFR(26) TFR(6)
    x0 += k1;  x1 += ks2 + 1u;
    TFR(17) TFR(29) TFR(16) TFR(24)
    x0 += ks2; x1 += k0 + 2u;
    TFR(13) TFR(15) TFR(26) TFR(6)
    x0 += k0;  x1 += k1 + 3u;
    TFR(17) TFR(29) TFR(16) TFR(24)
    x0 += k1;  x1 += ks2 + 4u;
    TFR(13) TFR(15) TFR(26) TFR(6)
    x0 += ks2; x1 += k0 + 5u;
#undef TFR
    o0 = x0; o1 = x1;
}

__device__ __forceinline__ float gumbel_from_bits(uint32_t b) {
    float u = __uint_as_float(0x3F800000u | (b >> 9)) - 1.0f;
    return -logf(-logf(u + 1e-6f) + 1e-6f);
}

// bf16 hi/lo split helpers
__device__ __forceinline__ void bf16_split(float v, uint16_t& h, uint16_t& l) {
    __nv_bfloat16 hb = __float2bfloat16(v);
    float lr = v - __bfloat162float(hb);
    __nv_bfloat16 lb = __float2bfloat16(lr);
    h = *reinterpret_cast<uint16_t*>(&hb);
    l = *reinterpret_cast<uint16_t*>(&lb);
}

__device__ __forceinline__ void mma_bf16(float* c, const uint32_t* a, const uint32_t* b) {
    asm volatile(
        "mma.sync.aligned.m16n8k16.row.col.f32.bf16.bf16.f32 "
        "{%0,%1,%2,%3},{%4,%5,%6,%7},{%8,%9},{%0,%1,%2,%3};"
        : "+f"(c[0]), "+f"(c[1]), "+f"(c[2]), "+f"(c[3])
        : "r"(a[0]), "r"(a[1]), "r"(a[2]), "r"(a[3]), "r"(b[0]), "r"(b[1]));
}

// ---------------- prep: Wn -> packed bf16x2 hi/lo [kp][n] --------------
__global__ void prep_kernel(const float* __restrict__ Wn) {
    int idx = blockIdx.x * 256 + threadIdx.x;
    if (idx >= DDP * DD) return;
    int kp = idx / DD;
    int n  = idx % DD;
    float v0 = Wn[(size_t)(2 * kp) * DD + n];
    float v1 = Wn[(size_t)(2 * kp + 1) * DD + n];
    uint16_t h0, l0, h1, l1;
    bf16_split(v0, h0, l0);
    bf16_split(v1, h1, l1);
    g_WnHP[idx] = (uint32_t)h0 | ((uint32_t)h1 << 16);
    g_WnLP[idx] = (uint32_t)l0 | ((uint32_t)l1 << 16);
}

// ---------------- kernel: step-invariant base distance ----------------
__global__ void based_kernel(const float* __restrict__ prev_pos,
                             const float* __restrict__ disto,
                             const int* __restrict__ resi,
                             const int* __restrict__ chain,
                             const int* __restrict__ batch) {
    int gid = blockIdx.x * blockDim.x + threadIdx.x;
    if (gid >= NN * BSZ) return;
    int i  = gid >> 8;
    int jj = gid & 255;
    int b  = batch[i];
    int j  = b * BSZ + jj;

    const float4* dp = (const float4*)(disto + ((size_t)i * NN + j) * NBINS);
    float4 v[16];
    float mx = -1e30f;
#pragma unroll
    for (int q = 0; q < 16; q++) {
        v[q] = dp[q];
        mx = fmaxf(mx, fmaxf(fmaxf(v[q].x, v[q].y), fmaxf(v[q].z, v[q].w)));
    }
    const float step = 22.0f / 64.0f;
    float se = 0.0f, swc = 0.0f;
#pragma unroll
    for (int q = 0; q < 16; q++) {
        float e0 = expf(v[q].x - mx), e1 = expf(v[q].y - mx);
        float e2 = expf(v[q].z - mx), e3 = expf(v[q].w - mx);
        se  += e0 + e1 + e2 + e3;
        swc += e0 * (step * (4*q + 0) + 0.5f*step)
             + e1 * (step * (4*q + 1) + 0.5f*step)
             + e2 * (step * (4*q + 2) + 0.5f*step)
             + e3 * (step * (4*q + 3) + 0.5f*step);
    }
    float md = swc / se;

    float d = __int_as_float(0x7f800000);
    if (chain[i] == chain[j]) {
        d = fabsf((float)(resi[i] - resi[j])) * 3.81f;
    }
    if (md < 8.0f) d = fminf(d, md);

    float dx = prev_pos[i * POSW + 3] - prev_pos[j * POSW + 3];
    float dy = prev_pos[i * POSW + 4] - prev_pos[j * POSW + 4];
    float dz = prev_pos[i * POSW + 5] - prev_pos[j * POSW + 5];
    d = fminf(d, sqrtf(dx * dx + dy * dy + dz * dz));

    g_based[gid] = d;
}

// -------- fused top-K (hybrid shfl bitonic) + gather -> packed msg -----
__global__ void __launch_bounds__(384) topk_msg_kernel(uint32_t k0, uint32_t k1,
                                                       const int* __restrict__ batch) {
    int i   = blockIdx.x;
    int tid = threadIdx.x;                                 // 384 threads
    int b   = batch[i];
    bool act = tid < BSZ;

    __shared__ unsigned long long s[2][BSZ];               // dual-buffer
    __shared__ int sidx[KK];

    unsigned long long K = ~0ull;
    if (act) {
        int jj = tid;
        int j  = b * BSZ + jj;
        float cx = g_pos[i * POSW + 3], cy = g_pos[i * POSW + 4], cz = g_pos[i * POSW + 5];
        float dx = cx - g_pos[j * POSW + 3];
        float dy = cy - g_pos[j * POSW + 4];
        float dz = cz - g_pos[j * POSW + 5];
        float d  = fminf(g_based[i * BSZ + jj], sqrtf(dx * dx + dy * dy + dz * dz));

        uint32_t o0, o1;
        tf2x32(k0, k1, 0u, (uint32_t)(i * NN + j), o0, o1);
        float g = gumbel_from_bits(o0 ^ o1);
        float rd = 3.0f * d - g;

        uint32_t ub = __float_as_uint(rd);
        ub = (ub & 0x80000000u) ? ~ub : (ub | 0x80000000u);
        K = ((unsigned long long)ub << 32) | (unsigned)tid;
    }

    int sb = 0;
    for (unsigned k = 2; k <= BSZ; k <<= 1) {
        bool up = ((tid & k) == 0);
        for (unsigned st = k >> 1; st > 0; st >>= 1) {
            if (st >= 32) {
                if (act) s[sb][tid] = K;
                __syncthreads();                           // one sync: next smem
                unsigned long long other = act ? s[sb][tid ^ st] : 0ull;   // stage uses other buffer
                sb ^= 1;
                if (act) {
                    bool lower = ((tid & st) == 0);
                    bool keepmin = (up == lower);
                    K = keepmin ? (K < other ? K : other) : (K > other ? K : other);
                }
            } else if (act) {
                unsigned long long other = __shfl_xor_sync(0xFFFFFFFFu, K, st);
                bool lower = ((tid & st) == 0);
                bool keepmin = (up == lower);
                K = keepmin ? (K < other ? K : other) : (K > other ? K : other);
            }
        }
    }

    if (tid < KK)
        sidx[tid] = b * BSZ + (int)(K & 0xffffffffu);
    __syncthreads();

    float acc = 0.0f;
#pragma unroll 8
    for (int k = 0; k < KK; k++)
        acc += g_local[sidx[k] * DD + tid];
    float m = acc * (1.0f / 64.0f);

    uint16_t h, l;
    bf16_split(m, h, l);
    uint32_t ho = __shfl_xor_sync(0xFFFFFFFFu, (uint32_t)h, 1);
    uint32_t lo = __shfl_xor_sync(0xFFFFFFFFu, (uint32_t)l, 1);
    if ((tid & 1) == 0) {
        g_msgHP[i * DDP + (tid >> 1)] = (uint32_t)h | (ho << 16);
        g_msgLP[i * DDP + (tid >> 1)] = (uint32_t)l | (lo << 16);
    }
}

// -------- main GEMM: local += gelu(msg @ Wn), bf16x3 (R13 config) ------
__device__ __forceinline__ float gelu_tanh(float x) {
    float x3 = x * x * x;
    float t = tanhf(0.7978845608028654f * (x + 0.044715f * x3));
    return 0.5f * x * (1.0f + t);
}

#define KPB   16   // packed k-pairs per k-block (= 32 floats)
#define AST   20   // A[m][kp] stride: 20 ≡ 4 mod 32 -> conflict-free
#define BSTN  72   // B[kp][n] stride: 72 ≡ 8 mod 32 -> conflict-free
#define NKIT  (DDP / KPB)   // 12

// dynamic smem layout (uint32 units)
#define U_AH  0
#define U_AL  (U_AH + 2 * 64 * AST)     // 2560
#define U_BH  (U_AL + 2 * 64 * AST)     // 5120
#define U_BL  (U_BH + 2 * KPB * BSTN)   // 7424
#define U_WP  (U_BL + 2 * KPB * BSTN)   // 9728
#define SMEM_U32 (U_WP + 64 * POSW)     // 10688 -> 42752 B
// red scratch (epilogue) aliases the dead A tiles: floats [64 rows][4 q][15]
// = 3840 floats, fits in [U_AH, U_BH) = 5120 u32.

__global__ void __launch_bounds__(512) gemm_gelu_tc(const float* __restrict__ Wp) {
    extern __shared__ uint32_t dsm[];
    uint32_t* AsH = dsm + U_AH;
    uint32_t* AsL = dsm + U_AL;
    uint32_t* BsH = dsm + U_BH;
    uint32_t* BsL = dsm + U_BL;
    float*    WpS = (float*)(dsm + U_WP);
    float*    red = (float*)dsm;                 // epilogue alias

    int tid  = threadIdx.x;
    int warp = tid >> 5, lane = tid & 31;
    int wm = (warp & 3) * 16;            // 16 warps: 4x4 grid of 16x16 tiles
    int wn = (warp >> 2) * 16;
    int row0 = blockIdx.y * 64;
    int col0 = blockIdx.x * 64;
    int g  = lane >> 2;
    int tg = lane & 3;

    float accA[2][4] = {};               // kp block 0..7
    float accB[2][4] = {};               // kp block 8..15

    // staging (512 threads, 8 bytes each)
    int am  = tid >> 3;            // 0..63
    int akp = (tid & 7) * 2;       // 0..14
    int bkp = tid >> 5;            // 0..15
    int bn  = (tid & 31) * 2;      // 0..62

    uint32_t sah[2], sal[2], sbh[2], sbl[2];
#pragma unroll
    for (int u = 0; u < 2; u++) {
        sah[u] = (uint32_t)__cvta_generic_to_shared(&AsH[u * 64 * AST + am * AST + akp]);
        sal[u] = (uint32_t)__cvta_generic_to_shared(&AsL[u * 64 * AST + am * AST + akp]);
        sbh[u] = (uint32_t)__cvta_generic_to_shared(&BsH[u * KPB * BSTN + bkp * BSTN + bn]);
        sbl[u] = (uint32_t)__cvta_generic_to_shared(&BsL[u * KPB * BSTN + bkp * BSTN + bn]);
    }

#define GSTAGE(it, buf)                                                          \
    {                                                                            \
        int k0p = (it) * KPB;                                                    \
        const uint32_t* pah = &g_msgHP[(row0 + am) * DDP + k0p + akp];           \
        asm volatile("cp.async.ca.shared.global [%0],[%1],8;" :: "r"(sah[buf]), "l"(pah)); \
        const uint32_t* pal = &g_msgLP[(row0 + am) * DDP + k0p + akp];           \
        asm volatile("cp.async.ca.shared.global [%0],[%1],8;" :: "r"(sal[buf]), "l"(pal)); \
        const uint32_t* pbh = &g_WnHP[(size_t)(k0p + bkp) * DD + col0 + bn];     \
        asm volatile("cp.async.ca.shared.global [%0],[%1],8;" :: "r"(sbh[buf]), "l"(pbh)); \
        const uint32_t* pbl = &g_WnLP[(size_t)(k0p + bkp) * DD + col0 + bn];     \
        asm volatile("cp.async.ca.shared.global [%0],[%1],8;" :: "r"(sbl[buf]), "l"(pbl)); \
        asm volatile("cp.async.commit_group;");                                  \
    }

    GSTAGE(0, 0)

    for (int idx = tid; idx < 64 * POSW; idx += 512)
        WpS[idx] = Wp[col0 * POSW + idx];

    for (int it = 0; it < NKIT; ++it) {
        int cur = it & 1;
        if (it + 1 < NKIT) {
            GSTAGE(it + 1, !cur)
            asm volatile("cp.async.wait_group 1;");
        } else {
            asm volatile("cp.async.wait_group 0;");
        }
        __syncthreads();

        const uint32_t* AH = AsH + cur * 64 * AST;
        const uint32_t* AL = AsL + cur * 64 * AST;
        const uint32_t* BH = BsH + cur * KPB * BSTN;
        const uint32_t* BL = BsL + cur * KPB * BSTN;
#pragma unroll
        for (int ksp = 0; ksp < KPB; ksp += 8) {       // kp octets (k16 per MMA)
            float (*acc)[4] = (ksp == 0) ? accA : accB;
            uint32_t ah[4] = {
                AH[(wm + g) * AST + ksp + tg],
                AH[(wm + g + 8) * AST + ksp + tg],
                AH[(wm + g) * AST + ksp + tg + 4],
                AH[(wm + g + 8) * AST + ksp + tg + 4] };
            uint32_t al[4] = {
                AL[(wm + g) * AST + ksp + tg],
                AL[(wm + g + 8) * AST + ksp + tg],
                AL[(wm + g) * AST + ksp + tg + 4],
                AL[(wm + g + 8) * AST + ksp + tg + 4] };
#pragma unroll
            for (int nj = 0; nj < 2; nj++) {
                int cc = wn + nj * 8 + g;
                uint32_t bh[2] = { BH[(ksp + tg) * BSTN + cc],
                                   BH[(ksp + tg + 4) * BSTN + cc] };
                uint32_t bl[2] = { BL[(ksp + tg) * BSTN + cc],
                                   BL[(ksp + tg + 4) * BSTN + cc] };
                mma_bf16(acc[nj], al, bh);
                mma_bf16(acc[nj], ah, bl);
                mma_bf16(acc[nj], ah, bh);
            }
        }
        __syncthreads();
    }

    // merge split accumulators
#pragma unroll
    for (int nj = 0; nj < 2; nj++)
#pragma unroll
        for (int q = 0; q < 4; q++)
            accA[nj][q] += accB[nj][q];

    // epilogue: local += gelu(acc); pos partials
    int r = row0 + wm + g;
    float pp0[POSW], pp1[POSW];
#pragma unroll
    for (int o = 0; o < POSW; o++) { pp0[o] = 0.0f; pp1[o] = 0.0f; }

#pragma unroll
    for (int nj = 0; nj < 2; nj++) {
        int cl = wn + nj * 8 + 2 * tg;
        int c  = col0 + cl;
        float v00 = g_local[r * DD + c]           + gelu_tanh(accA[nj][0]);
        float v01 = g_local[r * DD + c + 1]       + gelu_tanh(accA[nj][1]);
        float v10 = g_local[(r + 8) * DD + c]     + gelu_tanh(accA[nj][2]);
        float v11 = g_local[(r + 8) * DD + c + 1] + gelu_tanh(accA[nj][3]);
        g_local[r * DD + c]           = v00;
        g_local[r * DD + c + 1]       = v01;
        g_local[(r + 8) * DD + c]     = v10;
        g_local[(r + 8) * DD + c + 1] = v11;
#pragma unroll
        for (int o = 0; o < POSW; o++) {
            float w0 = WpS[cl * POSW + o];
            float w1 = WpS[(cl + 1) * POSW + o];
            pp0[o] += v00 * w0 + v01 * w1;
            pp1[o] += v10 * w0 + v11 * w1;
        }
    }

#pragma unroll
    for (int dlt = 1; dlt <= 2; dlt <<= 1)
#pragma unroll
        for (int o = 0; o < POSW; o++) {
            pp0[o] += __shfl_xor_sync(0xFFFFFFFFu, pp0[o], dlt);
            pp1[o] += __shfl_xor_sync(0xFFFFFFFFu, pp1[o], dlt);
        }

    // cross-warp reduction over the 4 N-quarters via smem (aliased A tiles)
    int quarter = wn >> 4;   // 0..3
    if (tg == 0) {
        int lr0 = wm + g;                      // local row 0..63
#pragma unroll
        for (int o = 0; o < POSW; o++) {
            red[(lr0)     * 60 + quarter * POSW + o] = pp0[o];
            red[(lr0 + 8) * 60 + quarter * POSW + o] = pp1[o];
        }
    }
    __syncthreads();

    // 64 rows x 15 outputs = 960 sums-of-4; 512 threads, 2 items each
    for (int idx = tid; idx < 64 * POSW; idx += 512) {
        int row = idx / POSW;
        int o   = idx % POSW;
        float sum = red[row * 60 + o] + red[row * 60 + POSW + o]
                  + red[row * 60 + 2 * POSW + o] + red[row * 60 + 3 * POSW + o];
        g_pospart[(size_t)blockIdx.x * (NN * POSW) + (row0 + row) * POSW + o] = sum;
    }
}

// ---------------- kernel: finalize pos + trajectory write --------------
__global__ void __launch_bounds__(256) finalize_pos(float* __restrict__ traj_out) {
    int gidx = blockIdx.x * 256 + threadIdx.x;             // 60 x 256 = 15360
    float acc = 0.0f;
#pragma unroll
    for (int cb = 0; cb < NPART; cb++)
        acc += g_pospart[(size_t)cb * (NN * POSW) + gidx];
    float p = g_pos[gidx] + 0.1f * acc;
    g_pos[gidx] = p;
    traj_out[gidx] = p;
}

// ---------------- launch ----------------
extern "C" void kernel_launch(void* const* d_in, const int* in_sizes, int n_in,
                              void* d_out, int out_size) {
    const float* local    = (const float*)d_in[0];
    const float* pos      = (const float*)d_in[1];
    const float* prev_pos = (const float*)d_in[2];
    const float* disto    = (const float*)d_in[3];
    const float* Wn       = (const float*)d_in[4];
    const float* Wp       = (const float*)d_in[5];
    const int*   resi     = (const int*)d_in[6];
    const int*   chain    = (const int*)d_in[7];
    const int*   batch    = (const int*)d_in[8];
    float* out = (float*)d_out;

    cudaMemcpyToSymbolAsync(g_local, local, (size_t)NN * DD * sizeof(float), 0,
                            cudaMemcpyDeviceToDevice, 0);
    cudaMemcpyToSymbolAsync(g_pos, pos, (size_t)NN * POSW * sizeof(float), 0,
                            cudaMemcpyDeviceToDevice, 0);

    prep_kernel<<<(DDP * DD + 255) / 256, 256>>>(Wn);
    based_kernel<<<NN * BSZ / 256, 256>>>(prev_pos, disto, resi, chain, batch);

    uint32_t fk0[NDEPTH], fk1[NDEPTH];
    for (int t = 0; t < NDEPTH; t++)
        tf2x32(0u, 42u, 0u, (uint32_t)t, fk0[t], fk1[t]);

    float* traj_base = out + (size_t)NN * DD + (size_t)NN * POSW;
    dim3 ggrid(DD / 64, NN / 64);   // (6, 16) = 96 CTAs

    for (int t = 0; t < NDEPTH; t++) {
        topk_msg_kernel<<<NN, 384>>>(fk0[t], fk1[t], batch);
        gemm_gelu_tc<<<ggrid, 512, SMEM_U32 * sizeof(uint32_t)>>>(Wp);
        finalize_pos<<<NN * POSW / 256, 256>>>(traj_base + (size_t)t * NN * POSW);
    }

    cudaMemcpyFromSymbolAsync(out, g_local, (size_t)NN * DD * sizeof(float), 0,
                              cudaMemcpyDeviceToDevice, 0);
    cudaMemcpyFromSymbolAsync(out + (size_t)NN * DD, g_pos,
                              (size_t)NN * POSW * sizeof(float), 0,
                              cudaMemcpyDeviceToDevice, 0);
}